// round 7
// baseline (speedup 1.0000x reference)
#include <cuda_runtime.h>
#include <math.h>

#define N_TOK 2000
#define C_DIM 256
#define C3    768
#define H_NUM 8
#define ROWS  8
#define NCTA  250     // 2000/8
#define NTILE 32      // ceil(2000/64)

// ---------------- scratch (static device globals; no allocation) ----------------
static __device__ float g_yc[N_TOK * C3];           // qkv_cls  [2000,768]
static __device__ float g_yr[N_TOK * C3];           // qkv_reg
static __device__ float g_qnc[N_TOK * C_DIM];       // normalized q_cls
static __device__ float g_knc[N_TOK * C_DIM];
static __device__ float g_qnr[N_TOK * C_DIM];
static __device__ float g_knr[N_TOK * C_DIM];
static __device__ float g_vn [N_TOK * C_DIM];       // normalized v_cls

// ---------------- warp reductions ----------------
__device__ __forceinline__ float warpSum(float v) {
    #pragma unroll
    for (int o = 16; o; o >>= 1) v += __shfl_xor_sync(0xffffffffu, v, o);
    return v;
}

// ---------------- GEMM NN:  C[M,N] = A[M,K] * B[K,N] ----------------
__global__ void sgemm_nn(const float* __restrict__ A, const float* __restrict__ B,
                         float* __restrict__ C, int M, int Nn, int K,
                         int lda, int ldb, int ldc) {
    __shared__ float As[64][33];
    __shared__ float Bs[32][65];
    int tid = threadIdx.x;
    int tx = tid & 15, ty = tid >> 4;
    int m0 = blockIdx.y * 64, n0 = blockIdx.x * 64;
    float acc[4][4] = {};
    for (int k0 = 0; k0 < K; k0 += 32) {
        #pragma unroll
        for (int p = 0; p < 8; ++p) {
            int idx = tid + p * 256;
            int r = idx >> 5, k = idx & 31;
            As[r][k] = (m0 + r < M) ? A[(size_t)(m0 + r) * lda + k0 + k] : 0.f;
            int kk = idx >> 6, nn = idx & 63;
            if (kk < 32)
                Bs[kk][nn] = (n0 + nn < Nn) ? B[(size_t)(k0 + kk) * ldb + n0 + nn] : 0.f;
        }
        __syncthreads();
        #pragma unroll
        for (int k = 0; k < 32; ++k) {
            float ra[4], rb[4];
            #pragma unroll
            for (int x = 0; x < 4; ++x) { ra[x] = As[ty * 4 + x][k]; rb[x] = Bs[k][tx * 4 + x]; }
            #pragma unroll
            for (int mi = 0; mi < 4; ++mi)
                #pragma unroll
                for (int ni = 0; ni < 4; ++ni) acc[mi][ni] += ra[mi] * rb[ni];
        }
        __syncthreads();
    }
    #pragma unroll
    for (int mi = 0; mi < 4; ++mi) {
        int gm = m0 + ty * 4 + mi;
        if (gm >= M) continue;
        #pragma unroll
        for (int ni = 0; ni < 4; ++ni) {
            int gn = n0 + tx * 4 + ni;
            if (gn < Nn) C[(size_t)gm * ldc + gn] = acc[mi][ni];
        }
    }
}

// ---------------- per-head L2 normalize + x_ori copy ----------------
__device__ __forceinline__ float normed_val(const float* __restrict__ src, int base, int t) {
    float v = src[base + t];
    float ss = warpSum(v * v);          // warp == one 32-dim head segment
    return v / (sqrtf(ss) + 1e-8f);
}
__global__ void normalize_kernel(const float* __restrict__ yc, const float* __restrict__ yr,
                                 float* __restrict__ out) {
    int n = blockIdx.x;
    int t = threadIdx.x;                // 256 threads, 8 warps == 8 heads
    int b = n * C3;
    g_qnc[n * C_DIM + t] = normed_val(yc, b + 0,   t);
    g_knc[n * C_DIM + t] = normed_val(yc, b + 256, t);
    g_vn [n * C_DIM + t] = normed_val(yc, b + 512, t);
    g_qnr[n * C_DIM + t] = normed_val(yr, b + 0,   t);
    g_knr[n * C_DIM + t] = normed_val(yr, b + 256, t);
    out[(size_t)n * 512 + 256 + t] = yc[b + 512 + t];   // x_ori half of x_out
}

// ================= mega-fused attention kernel =================
// smem float layout:
//   [0      .. 16000) expc      (8 rows x 2000)   | phase C: chunk buffers cb0/cb1
//   [16000  .. 32000) expr                        |  (2 x 64x132 = 16896 spans both)
//   [32000  .. 48000) simb      (8 rows x 2000)
//   [48000  .. 57920) scratch:
//        A: q[512] + ktiles 2buf x 2br x (64*36)   (512 + 9216)
//        B: vtiles 2buf x (64*36) @+512, pbuf[512] @+5120, pav[2048] @+5632
//        C: vq[2048] @+0
//   [57920  .. 57952) misc: [0..15] ssum/inv (cls 8, reg 8); [16..23] s2inv; [24..31] tot
#define SMEM_FLOATS 57960

__global__ __launch_bounds__(256, 1) void fused_attn(float* __restrict__ out,
                                                     float* __restrict__ out_sim) {
    extern __shared__ float sm[];
    float* expc = sm;
    float* expr = sm + 16000;
    float* simb = sm + 32000;
    float* scr  = sm + 48000;
    float* misc = sm + 57920;

    const int tid  = threadIdx.x;
    const int lane = tid & 31;
    const int i0   = blockIdx.x * ROWS;

    // thread map for score phase (A)
    const int b    = tid >> 7;       // 0=cls, 1=reg
    const int bt   = tid & 127;
    const int jx   = bt & 63;        // j within 64-tile
    const int rg   = bt >> 6;        // row group (0..1)
    const int row0 = rg * 4;         // phase A: rows row0..row0+3
    // phase C thread map: 256 threads = 4 row-pairs x 64 j
    const int rgc  = tid >> 6;       // 0..3 -> rows rgc and rgc+4
    const int jxc  = tid & 63;
    // AV thread map
    const int d_av  = tid & 31;
    const int jg_av = tid >> 5;

    // zero sim accumulator
    for (int k = tid; k < ROWS * N_TOK; k += 256) simb[k] = 0.f;

    float4 kra0[2], kra1[2];   // k prefetch regs (cls / reg)
    const int pv  = tid;       // load-index helpers
    const int pjr = pv >> 3, pcc = (pv & 7) * 4;          // 64x32 tile: 2 f4/thread
    const int pjr2 = (pv + 256) >> 3, pcc2 = ((pv + 256) & 7) * 4;

    for (int h = 0; h < H_NUM; ++h) {
        // ---------------- phase A: scores -> exp -> row sums ----------------
        __syncthreads();   // previous phase done with scr
        {   // prefetch k tile 0
            int jj0 = pjr, jj1 = pjr2;
            const float4 z4 = {0.f, 0.f, 0.f, 0.f};
            kra0[0] = (jj0 < N_TOK) ? *(const float4*)&g_knc[jj0 * C_DIM + h * 32 + pcc]  : z4;
            kra0[1] = (jj1 < N_TOK) ? *(const float4*)&g_knc[jj1 * C_DIM + h * 32 + pcc2] : z4;
            kra1[0] = (jj0 < N_TOK) ? *(const float4*)&g_knr[jj0 * C_DIM + h * 32 + pcc]  : z4;
            kra1[1] = (jj1 < N_TOK) ? *(const float4*)&g_knr[jj1 * C_DIM + h * 32 + pcc2] : z4;
        }
        {   // q rows + zero sums
            int r = tid >> 5, kk = tid & 31;
            scr[tid]       = g_qnc[(i0 + r) * C_DIM + h * 32 + kk];
            scr[256 + tid] = g_qnr[(i0 + r) * C_DIM + h * 32 + kk];
            if (tid < 16) misc[tid] = 0.f;
        }
        {   // store k tile 0
            float* kb = scr + 512;
            *(float4*)&kb[pjr * 36 + pcc]        = kra0[0];
            *(float4*)&kb[pjr2 * 36 + pcc2]      = kra0[1];
            *(float4*)&kb[2304 + pjr * 36 + pcc]   = kra1[0];
            *(float4*)&kb[2304 + pjr2 * 36 + pcc2] = kra1[1];
        }
        __syncthreads();

        float ps0 = 0.f, ps1 = 0.f, ps2 = 0.f, ps3 = 0.f;
        for (int t = 0; t < NTILE; ++t) {
            if (t + 1 < NTILE) {   // prefetch next tile
                int base = (t + 1) * 64;
                int jj0 = base + pjr, jj1 = base + pjr2;
                const float4 z4 = {0.f, 0.f, 0.f, 0.f};
                kra0[0] = (jj0 < N_TOK) ? *(const float4*)&g_knc[jj0 * C_DIM + h * 32 + pcc]  : z4;
                kra0[1] = (jj1 < N_TOK) ? *(const float4*)&g_knc[jj1 * C_DIM + h * 32 + pcc2] : z4;
                kra1[0] = (jj0 < N_TOK) ? *(const float4*)&g_knr[jj0 * C_DIM + h * 32 + pcc]  : z4;
                kra1[1] = (jj1 < N_TOK) ? *(const float4*)&g_knr[jj1 * C_DIM + h * 32 + pcc2] : z4;
            }
            // compute current tile
            {
                const float* ks = scr + 512 + (t & 1) * 4608 + b * 2304;
                const float* qb = scr + b * 256;
                float c0 = 0.f, c1 = 0.f, c2 = 0.f, c3 = 0.f;
                #pragma unroll
                for (int kk = 0; kk < 32; kk += 4) {
                    float4 kv = *(const float4*)&ks[jx * 36 + kk];
                    float4 q0 = *(const float4*)&qb[(row0 + 0) * 32 + kk];
                    float4 q1 = *(const float4*)&qb[(row0 + 1) * 32 + kk];
                    float4 q2 = *(const float4*)&qb[(row0 + 2) * 32 + kk];
                    float4 q3 = *(const float4*)&qb[(row0 + 3) * 32 + kk];
                    c0 = fmaf(kv.x, q0.x, c0); c0 = fmaf(kv.y, q0.y, c0);
                    c0 = fmaf(kv.z, q0.z, c0); c0 = fmaf(kv.w, q0.w, c0);
                    c1 = fmaf(kv.x, q1.x, c1); c1 = fmaf(kv.y, q1.y, c1);
                    c1 = fmaf(kv.z, q1.z, c1); c1 = fmaf(kv.w, q1.w, c1);
                    c2 = fmaf(kv.x, q2.x, c2); c2 = fmaf(kv.y, q2.y, c2);
                    c2 = fmaf(kv.z, q2.z, c2); c2 = fmaf(kv.w, q2.w, c2);
                    c3 = fmaf(kv.x, q3.x, c3); c3 = fmaf(kv.y, q3.y, c3);
                    c3 = fmaf(kv.z, q3.z, c3); c3 = fmaf(kv.w, q3.w, c3);
                }
                int j = t * 64 + jx;
                if (j < N_TOK) {
                    float* eb = b ? expr : expc;
                    float e0 = __expf(c0 * 25.f - 25.f);
                    float e1 = __expf(c1 * 25.f - 25.f);
                    float e2 = __expf(c2 * 25.f - 25.f);
                    float e3 = __expf(c3 * 25.f - 25.f);
                    eb[(row0 + 0) * 2000 + j] = e0; ps0 += e0;
                    eb[(row0 + 1) * 2000 + j] = e1; ps1 += e1;
                    eb[(row0 + 2) * 2000 + j] = e2; ps2 += e2;
                    eb[(row0 + 3) * 2000 + j] = e3; ps3 += e3;
                }
            }
            if (t + 1 < NTILE) {   // store next tile
                float* kb = scr + 512 + ((t + 1) & 1) * 4608;
                *(float4*)&kb[pjr * 36 + pcc]          = kra0[0];
                *(float4*)&kb[pjr2 * 36 + pcc2]        = kra0[1];
                *(float4*)&kb[2304 + pjr * 36 + pcc]   = kra1[0];
                *(float4*)&kb[2304 + pjr2 * 36 + pcc2] = kra1[1];
            }
            __syncthreads();
        }
        // reduce row sums (warp spans 32 j's of same (b,rg))
        {
            float s;
            s = warpSum(ps0); if (lane == 0) atomicAdd(&misc[b * 8 + row0 + 0], s);
            s = warpSum(ps1); if (lane == 0) atomicAdd(&misc[b * 8 + row0 + 1], s);
            s = warpSum(ps2); if (lane == 0) atomicAdd(&misc[b * 8 + row0 + 2], s);
            s = warpSum(ps3); if (lane == 0) atomicAdd(&misc[b * 8 + row0 + 3], s);
        }
        __syncthreads();
        if (tid < 16) misc[tid] = 1.0f / misc[tid];   // invert sums
        __syncthreads();

        // ---------------- phase B: combine + mask + sim + AV ----------------
        float xav[8];
        #pragma unroll
        for (int r = 0; r < 8; ++r) xav[r] = 0.f;
        float* vb   = scr + 512;
        float* pbuf = scr + 5120;
        float* pav  = scr + 5632;
        {   // v tile 0
            const float4 z4 = {0.f, 0.f, 0.f, 0.f};
            kra0[0] = (pjr  < N_TOK) ? *(const float4*)&g_yc[(size_t)pjr  * C3 + 512 + h * 32 + pcc]  : z4;
            kra0[1] = (pjr2 < N_TOK) ? *(const float4*)&g_yc[(size_t)pjr2 * C3 + 512 + h * 32 + pcc2] : z4;
            *(float4*)&vb[pjr * 36 + pcc]   = kra0[0];
            *(float4*)&vb[pjr2 * 36 + pcc2] = kra0[1];
        }
        __syncthreads();
        for (int t = 0; t < NTILE; ++t) {
            if (t + 1 < NTILE) {
                int base = (t + 1) * 64;
                int jj0 = base + pjr, jj1 = base + pjr2;
                const float4 z4 = {0.f, 0.f, 0.f, 0.f};
                kra0[0] = (jj0 < N_TOK) ? *(const float4*)&g_yc[(size_t)jj0 * C3 + 512 + h * 32 + pcc]  : z4;
                kra0[1] = (jj1 < N_TOK) ? *(const float4*)&g_yc[(size_t)jj1 * C3 + 512 + h * 32 + pcc2] : z4;
            }
            // p = combined masked attention prob -> pbuf, sim accumulate
            #pragma unroll
            for (int cq = 0; cq < 2; ++cq) {
                int c = tid + cq * 256;
                int r = c >> 6, jxx = c & 63;
                int j = t * 64 + jxx;
                float p = 0.f;
                if (j < N_TOK) {
                    float pc = expc[r * 2000 + j] * misc[r];
                    float pr = expr[r * 2000 + j] * misc[8 + r];
                    p = 0.5f * (pc + pr);
                    int i = i0 + r, bs = (i / 10) * 10;
                    if (!((j == i) || (j < bs) || (j >= bs + 9))) p = 0.f;
                    simb[r * 2000 + j] += p;
                }
                pbuf[c] = p;
            }
            if (t + 1 < NTILE) {
                float* vbn = vb + ((t + 1) & 1) * 2304;
                *(float4*)&vbn[pjr * 36 + pcc]   = kra0[0];
                *(float4*)&vbn[pjr2 * 36 + pcc2] = kra0[1];
            }
            __syncthreads();
            // AV accumulate
            {
                const float* vc = vb + (t & 1) * 2304;
                #pragma unroll
                for (int jj = 0; jj < 8; ++jj) {
                    int jr = jg_av * 8 + jj;
                    float vv = vc[jr * 36 + d_av];
                    #pragma unroll
                    for (int r = 0; r < 8; ++r)
                        xav[r] = fmaf(pbuf[r * 64 + jr], vv, xav[r]);
                }
            }
            __syncthreads();
        }
        // reduce AV partials over jg and store x
        #pragma unroll
        for (int r = 0; r < 8; ++r) pav[jg_av * 256 + r * 32 + d_av] = xav[r];
        __syncthreads();
        {
            int r = tid >> 5, d = tid & 31;
            float s = 0.f;
            #pragma unroll
            for (int g = 0; g < 8; ++g) s += pav[g * 256 + tid];
            out[(size_t)(i0 + r) * 512 + h * 32 + d] = s;
        }
        // next head's top-of-loop sync protects scr
    }

    // ---------------- phase C: raw mask + sim_round2 ----------------
    __syncthreads();
    {   // load vn query rows (8 x 256) into scr[0..2047]
        #pragma unroll
        for (int p = 0; p < 2; ++p) {
            int v = tid + p * 256;
            int r = v >> 6, cc = (v & 63) * 4;
            *(float4*)&scr[r * 256 + cc] = *(const float4*)&g_vn[(i0 + r) * C_DIM + cc];
        }
    }
    {   // sums of exp(sim) per row (softmax denominator, offset 0: sim in [0,1])
        int w = tid >> 5;
        float s = 0.f;
        for (int j = lane; j < N_TOK; j += 32) s += __expf(simb[w * 2000 + j]);
        s = warpSum(s);
        if (lane == 0) misc[16 + w] = s;
    }
    __syncthreads();
    if (tid < 8)  misc[16 + tid] = 1.0f / misc[16 + tid];
    if (tid >= 8 && tid < 16) misc[16 + tid] = 0.f;   // misc[24..31] = tot accumulators
    // chunk pipeline: 32 tiles x 2 c-chunks over expc/expr region
    float* cb = sm;                    // 2 buffers of 64x132
    float4 creg[8];
    {   // prefetch chunk 0 (tile 0, c0 = 0)
        const float4 z4 = {0.f, 0.f, 0.f, 0.f};
        #pragma unroll
        for (int p = 0; p < 8; ++p) {
            int v = tid + p * 256;
            int jr = v >> 5, cc = (v & 31) * 4;
            creg[p] = (jr < N_TOK) ? *(const float4*)&g_vn[jr * C_DIM + cc] : z4;
        }
    }
    __syncthreads();
    #pragma unroll
    for (int p = 0; p < 8; ++p) {
        int v = tid + p * 256;
        int jr = v >> 5, cc = (v & 31) * 4;
        *(float4*)&cb[jr * 132 + cc] = creg[p];
    }
    __syncthreads();
    {
        float a0 = 0.f, a1 = 0.f, tp0 = 0.f, tp1 = 0.f;
        for (int s = 0; s < 64; ++s) {
            if (s + 1 < 64) {   // prefetch next chunk
                int tile = (s + 1) >> 1, c0 = ((s + 1) & 1) * 128;
                const float4 z4 = {0.f, 0.f, 0.f, 0.f};
                #pragma unroll
                for (int p = 0; p < 8; ++p) {
                    int v = tid + p * 256;
                    int jr = tile * 64 + (v >> 5), cc = (v & 31) * 4;
                    creg[p] = (jr < N_TOK) ? *(const float4*)&g_vn[jr * C_DIM + c0 + cc] : z4;
                }
            }
            {   // raw accumulate for this chunk (rows rgc, rgc+4)
                const float* cbu = cb + (s & 1) * 8448;
                const int c0 = (s & 1) * 128;
                #pragma unroll 8
                for (int cc = 0; cc < 128; cc += 4) {
                    float4 kv = *(const float4*)&cbu[jxc * 132 + cc];
                    float4 qa = *(const float4*)&scr[rgc * 256 + c0 + cc];
                    float4 qb2 = *(const float4*)&scr[(rgc + 4) * 256 + c0 + cc];
                    a0 = fmaf(kv.x, qa.x, a0);  a0 = fmaf(kv.y, qa.y, a0);
                    a0 = fmaf(kv.z, qa.z, a0);  a0 = fmaf(kv.w, qa.w, a0);
                    a1 = fmaf(kv.x, qb2.x, a1); a1 = fmaf(kv.y, qb2.y, a1);
                    a1 = fmaf(kv.z, qb2.z, a1); a1 = fmaf(kv.w, qb2.w, a1);
                }
            }
            if (s & 1) {   // tile complete: apply raw>6 mask, exp(sim)*inv
                int j = (s >> 1) * 64 + jxc;
                if (j < N_TOK) {
                    float t0 = 0.f, t1 = 0.f;
                    if (a0 > 6.0f) t0 = __expf(simb[rgc * 2000 + j]) * misc[16 + rgc];
                    if (a1 > 6.0f) t1 = __expf(simb[(rgc + 4) * 2000 + j]) * misc[16 + rgc + 4];
                    simb[rgc * 2000 + j] = t0;       tp0 += t0;
                    simb[(rgc + 4) * 2000 + j] = t1; tp1 += t1;
                }
                a0 = 0.f; a1 = 0.f;
            }
            if (s + 1 < 64) {   // store next chunk
                float* cbn = cb + ((s + 1) & 1) * 8448;
                #pragma unroll
                for (int p = 0; p < 8; ++p) {
                    int v = tid + p * 256;
                    int jr = v >> 5, cc = (v & 31) * 4;
                    *(float4*)&cbn[jr * 132 + cc] = creg[p];
                }
            }
            __syncthreads();
        }
        float s0 = warpSum(tp0);
        if (lane == 0) atomicAdd(&misc[24 + rgc], s0);
        float s1 = warpSum(tp1);
        if (lane == 0) atomicAdd(&misc[24 + rgc + 4], s1);
    }
    __syncthreads();
    if (tid < 8) misc[24 + tid] = 1.0f / (misc[24 + tid] + 1e-8f);
    __syncthreads();
    {   // final sim_round2 store
        int w = tid >> 5;
        float inv = misc[24 + w];
        for (int j = lane; j < N_TOK; j += 32)
            out_sim[(size_t)(i0 + w) * 2000 + j] = simb[w * 2000 + j] * inv;
    }
}

// ---------------- launch ----------------
extern "C" void kernel_launch(void* const* d_in, const int* in_sizes, int n_in,
                              void* d_out, int out_size) {
    const float* x_cls = (const float*)d_in[0];
    const float* x_reg = (const float*)d_in[1];
    const float* Wc    = (const float*)d_in[2];
    const float* Wr    = (const float*)d_in[3];
    float* out     = (float*)d_out;
    float* out_sim = out + (size_t)N_TOK * 512;

    float *yc, *yr;
    cudaGetSymbolAddress((void**)&yc, g_yc);
    cudaGetSymbolAddress((void**)&yr, g_yr);

    cudaFuncSetAttribute(fused_attn, cudaFuncAttributeMaxDynamicSharedMemorySize,
                         SMEM_FLOATS * 4);

    // 1) QKV projections
    sgemm_nn<<<dim3(12, 32), 256>>>(x_cls, Wc, yc, N_TOK, C3, C_DIM, C_DIM, C3, C3);
    sgemm_nn<<<dim3(12, 32), 256>>>(x_reg, Wr, yr, N_TOK, C3, C_DIM, C_DIM, C3, C3);

    // 2) per-head L2 normalize (+ write x_ori half of out)
    normalize_kernel<<<N_TOK, 256>>>(yc, yr, out);

    // 3) fully fused: scores -> softmax -> mask -> sim -> AV -> raw -> sim_round2
    fused_attn<<<NCTA, 256, SMEM_FLOATS * 4>>>(out, out_sim);
}

// round 11
// speedup vs baseline: 1.8114x; 1.8114x over previous
#include <cuda_runtime.h>
#include <math.h>

#define N_TOK 2000
#define C_DIM 256
#define C3    768
#define H_NUM 8
#define ROWS  8
#define NCTA  250
#define TPB   512
#define KT_LD 2048   // padded j-stride of transposed operands

// ---------------- scratch (static device globals; no allocation) ----------------
static __device__ float g_yc [N_TOK * C3];        // qkv_cls [2000,768]
static __device__ float g_yr [N_TOK * C3];        // qkv_reg
static __device__ float g_qnc[N_TOK * C_DIM];     // normalized q_cls, row-major
static __device__ float g_qnr[N_TOK * C_DIM];
static __device__ float g_vn [N_TOK * C_DIM];     // normalized v_cls, row-major
static __device__ float g_ktc[C_DIM * KT_LD];     // normalized k_cls, TRANSPOSED [chan][j]
static __device__ float g_ktr[C_DIM * KT_LD];     // normalized k_reg, transposed
static __device__ float g_vnt[C_DIM * KT_LD];     // normalized v_cls, transposed

__device__ __forceinline__ float warpSum(float v) {
    #pragma unroll
    for (int o = 16; o; o >>= 1) v += __shfl_xor_sync(0xffffffffu, v, o);
    return v;
}

// ---------------- GEMM NN:  C[M,N] = A[M,K] * B[K,N] ----------------
__global__ void sgemm_nn(const float* __restrict__ A, const float* __restrict__ B,
                         float* __restrict__ C, int M, int Nn, int K,
                         int lda, int ldb, int ldc) {
    __shared__ float As[64][33];
    __shared__ float Bs[32][65];
    int tid = threadIdx.x;
    int tx = tid & 15, ty = tid >> 4;
    int m0 = blockIdx.y * 64, n0 = blockIdx.x * 64;
    float acc[4][4] = {};
    for (int k0 = 0; k0 < K; k0 += 32) {
        #pragma unroll
        for (int p = 0; p < 8; ++p) {
            int idx = tid + p * 256;
            int r = idx >> 5, k = idx & 31;
            As[r][k] = (m0 + r < M) ? A[(size_t)(m0 + r) * lda + k0 + k] : 0.f;
            int kk = idx >> 6, nn = idx & 63;
            if (kk < 32)
                Bs[kk][nn] = (n0 + nn < Nn) ? B[(size_t)(k0 + kk) * ldb + n0 + nn] : 0.f;
        }
        __syncthreads();
        #pragma unroll
        for (int k = 0; k < 32; ++k) {
            float ra[4], rb[4];
            #pragma unroll
            for (int x = 0; x < 4; ++x) { ra[x] = As[ty * 4 + x][k]; rb[x] = Bs[k][tx * 4 + x]; }
            #pragma unroll
            for (int mi = 0; mi < 4; ++mi)
                #pragma unroll
                for (int ni = 0; ni < 4; ++ni) acc[mi][ni] += ra[mi] * rb[ni];
        }
        __syncthreads();
    }
    #pragma unroll
    for (int mi = 0; mi < 4; ++mi) {
        int gm = m0 + ty * 4 + mi;
        if (gm >= M) continue;
        #pragma unroll
        for (int ni = 0; ni < 4; ++ni) {
            int gn = n0 + tx * 4 + ni;
            if (gn < Nn) C[(size_t)gm * ldc + gn] = acc[mi][ni];
        }
    }
}

// ---------------- per-head L2 normalize + transposes + x_ori ----------------
__device__ __forceinline__ float normed_val(const float* __restrict__ src, int base, int t) {
    float v = src[base + t];
    float ss = warpSum(v * v);          // warp == one 32-dim head segment
    return v / (sqrtf(ss) + 1e-8f);
}
__global__ void normalize_kernel(const float* __restrict__ yc, const float* __restrict__ yr,
                                 float* __restrict__ out) {
    int n = blockIdx.x;
    int t = threadIdx.x;                // 256 threads, 8 warps == 8 heads
    int b = n * C3;
    float qc = normed_val(yc, b + 0,   t);  g_qnc[n * C_DIM + t] = qc;
    float kc = normed_val(yc, b + 256, t);  g_ktc[t * KT_LD + n] = kc;
    float vv = normed_val(yc, b + 512, t);  g_vn[n * C_DIM + t] = vv;
                                            g_vnt[t * KT_LD + n] = vv;
    float qr = normed_val(yr, b + 0,   t);  g_qnr[n * C_DIM + t] = qr;
    float kr = normed_val(yr, b + 256, t);  g_ktr[t * KT_LD + n] = kr;
    out[(size_t)n * 512 + 256 + t] = yc[b + 512 + t];   // x_ori half of x_out
}

// ================= mega-fused attention kernel (register-tiled) =================
// smem float layout:
//   [0     .. 16000) expc  (8 rows x 2000)   -> becomes combined masked p in phase B
//   [16000 .. 32000) expr
//   [32000 .. 48000) simb  (8 rows x 2000)
//   [48000 .. 48512) qs    (phase A: 2 branches x 8 rows x 32)
//   [48000 .. 50048) scrv  (phase C: 8 vn rows x 256)  -- overlaps qs (disjoint phases)
//   [50048 .. 54144) pav   (AV partials: 16 warps x 8r x 32d)
//   [54144 .. 54176) misc: [0..7] cls inv, [8..15] reg inv, [16..23] s2 inv, [24..31] tot inv
#define SMEM_FLOATS 54176

__global__ __launch_bounds__(TPB, 1) void fused_attn(float* __restrict__ out,
                                                     float* __restrict__ out_sim) {
    extern __shared__ float sm[];
    float* expc = sm;
    float* expr = sm + 16000;
    float* simb = sm + 32000;
    float* qs   = sm + 48000;
    float* scrv = sm + 48000;
    float* pav  = sm + 50048;
    float* misc = sm + 54144;

    const int tid  = threadIdx.x;
    const int lane = tid & 31;
    const int wrp  = tid >> 5;
    const int i0   = blockIdx.x * ROWS;

    // phase A map: branch x 256 j-threads (4 j each, 2 passes)
    const int bA = tid >> 8;            // 0=cls, 1=reg (warp-uniform)
    const int jt = tid & 255;
    const float* ktA = bA ? g_ktr : g_ktc;
    float* ebA = bA ? expr : expc;
    const int boff = bA * 256;

    // zero sim accumulator
    for (int k = tid; k < ROWS * N_TOK; k += TPB) simb[k] = 0.f;
    // (simb consumers are after phase-A's first __syncthreads)

    for (int h = 0; h < H_NUM; ++h) {
        // ======== phase A: scores -> exp -> row sums (no staging, stream k from L2) ========
        if (tid < 16) misc[tid] = 0.f;
        {   // load q tiles: 512 values = 2 branches x 8 rows x 32
            int b2 = tid >> 8, r = (tid >> 5) & 7, kk = tid & 31;
            const float* qsrc = b2 ? g_qnr : g_qnc;
            qs[tid] = qsrc[(i0 + r) * C_DIM + h * 32 + kk];
        }
        __syncthreads();

        float psum[ROWS];
        #pragma unroll
        for (int r = 0; r < ROWS; ++r) psum[r] = 0.f;

        #pragma unroll
        for (int pass = 0; pass < 2; ++pass) {
            int j = pass * 1024 + jt * 4;
            if (j < N_TOK) {
                float c[ROWS][4];
                #pragma unroll
                for (int r = 0; r < ROWS; ++r) { c[r][0]=0.f; c[r][1]=0.f; c[r][2]=0.f; c[r][3]=0.f; }
                const float* ktb = ktA + (size_t)(h * 32) * KT_LD + j;
                float4 kv0 = *(const float4*)&ktb[0 * KT_LD];
                float4 kv1 = *(const float4*)&ktb[1 * KT_LD];
                float4 kv2 = *(const float4*)&ktb[2 * KT_LD];
                float4 kv3 = *(const float4*)&ktb[3 * KT_LD];
                #pragma unroll
                for (int ch = 0; ch < 8; ++ch) {
                    float4 n0, n1, n2, n3;
                    if (ch < 7) {
                        const float* p = ktb + (size_t)((ch + 1) * 4) * KT_LD;
                        n0 = *(const float4*)&p[0 * KT_LD];
                        n1 = *(const float4*)&p[1 * KT_LD];
                        n2 = *(const float4*)&p[2 * KT_LD];
                        n3 = *(const float4*)&p[3 * KT_LD];
                    }
                    #pragma unroll
                    for (int r = 0; r < ROWS; ++r) {
                        float4 q = *(const float4*)&qs[boff + r * 32 + ch * 4];
                        c[r][0] = fmaf(q.x, kv0.x, c[r][0]); c[r][0] = fmaf(q.y, kv1.x, c[r][0]);
                        c[r][0] = fmaf(q.z, kv2.x, c[r][0]); c[r][0] = fmaf(q.w, kv3.x, c[r][0]);
                        c[r][1] = fmaf(q.x, kv0.y, c[r][1]); c[r][1] = fmaf(q.y, kv1.y, c[r][1]);
                        c[r][1] = fmaf(q.z, kv2.y, c[r][1]); c[r][1] = fmaf(q.w, kv3.y, c[r][1]);
                        c[r][2] = fmaf(q.x, kv0.z, c[r][2]); c[r][2] = fmaf(q.y, kv1.z, c[r][2]);
                        c[r][2] = fmaf(q.z, kv2.z, c[r][2]); c[r][2] = fmaf(q.w, kv3.z, c[r][2]);
                        c[r][3] = fmaf(q.x, kv0.w, c[r][3]); c[r][3] = fmaf(q.y, kv1.w, c[r][3]);
                        c[r][3] = fmaf(q.z, kv2.w, c[r][3]); c[r][3] = fmaf(q.w, kv3.w, c[r][3]);
                    }
                    kv0 = n0; kv1 = n1; kv2 = n2; kv3 = n3;
                }
                #pragma unroll
                for (int r = 0; r < ROWS; ++r) {
                    float4 e;
                    e.x = __expf(fmaf(c[r][0], 25.f, -25.f));
                    e.y = __expf(fmaf(c[r][1], 25.f, -25.f));
                    e.z = __expf(fmaf(c[r][2], 25.f, -25.f));
                    e.w = __expf(fmaf(c[r][3], 25.f, -25.f));
                    *(float4*)&ebA[r * 2000 + j] = e;
                    psum[r] += (e.x + e.y) + (e.z + e.w);
                }
            }
        }
        #pragma unroll
        for (int r = 0; r < ROWS; ++r) {
            float s = warpSum(psum[r]);
            if (lane == 0) atomicAdd(&misc[bA * 8 + r], s);
        }
        __syncthreads();
        if (tid < 16) misc[tid] = 1.0f / misc[tid];
        __syncthreads();

        // ======== phase B1: combine + mask (p overwrites expc) + sim accumulate ========
        for (int idx = tid; idx < 4000; idx += TPB) {   // 4000 float4 groups
            int r = idx / 500;
            int j = (idx - r * 500) * 4;
            float4 ec = *(const float4*)&expc[r * 2000 + j];
            float4 er = *(const float4*)&expr[r * 2000 + j];
            float ic = misc[r], ir = misc[8 + r];
            float4 p;
            p.x = 0.5f * fmaf(ec.x, ic, er.x * ir);
            p.y = 0.5f * fmaf(ec.y, ic, er.y * ir);
            p.z = 0.5f * fmaf(ec.z, ic, er.z * ir);
            p.w = 0.5f * fmaf(ec.w, ic, er.w * ir);
            int i = i0 + r, bs = (i / 10) * 10;
            if (!((j + 0 == i) || (j + 0 < bs) || (j + 0 >= bs + 9))) p.x = 0.f;
            if (!((j + 1 == i) || (j + 1 < bs) || (j + 1 >= bs + 9))) p.y = 0.f;
            if (!((j + 2 == i) || (j + 2 < bs) || (j + 2 >= bs + 9))) p.z = 0.f;
            if (!((j + 3 == i) || (j + 3 < bs) || (j + 3 >= bs + 9))) p.w = 0.f;
            float4 sb = *(const float4*)&simb[r * 2000 + j];
            sb.x += p.x; sb.y += p.y; sb.z += p.z; sb.w += p.w;
            *(float4*)&simb[r * 2000 + j] = sb;
            *(float4*)&expc[r * 2000 + j] = p;
        }
        __syncthreads();

        // ======== phase B2: AV (x = p @ v), 16 warps x 128-j slices ========
        {
            int jbase = wrp * 128;
            int cnt = N_TOK - jbase; if (cnt > 128) cnt = 128;
            float acc[ROWS];
            #pragma unroll
            for (int r = 0; r < ROWS; ++r) acc[r] = 0.f;
            const float* vp = g_yc + 512 + h * 32 + lane;
            for (int jj = 0; jj < cnt; jj += 4) {
                int j = jbase + jj;
                float v0 = vp[(size_t)(j + 0) * C3];
                float v1 = vp[(size_t)(j + 1) * C3];
                float v2 = vp[(size_t)(j + 2) * C3];
                float v3 = vp[(size_t)(j + 3) * C3];
                #pragma unroll
                for (int r = 0; r < ROWS; ++r) {
                    float4 p = *(const float4*)&expc[r * 2000 + j];   // broadcast
                    acc[r] = fmaf(p.x, v0, acc[r]);
                    acc[r] = fmaf(p.y, v1, acc[r]);
                    acc[r] = fmaf(p.z, v2, acc[r]);
                    acc[r] = fmaf(p.w, v3, acc[r]);
                }
            }
            #pragma unroll
            for (int r = 0; r < ROWS; ++r) pav[wrp * 256 + r * 32 + lane] = acc[r];
        }
        __syncthreads();
        if (tid < 256) {
            int r = tid >> 5, d = tid & 31;
            float s = 0.f;
            #pragma unroll
            for (int w2 = 0; w2 < 16; ++w2) s += pav[w2 * 256 + tid];
            out[(size_t)(i0 + r) * 512 + h * 32 + d] = s;
        }
        __syncthreads();
    }

    // ======== phase C: raw = vn.vn^T mask + sim_round2 ========
    {   // vn rows of this block -> scrv (8 x 256)
        int r = tid >> 6, cc = (tid & 63) * 4;
        *(float4*)&scrv[r * 256 + cc] = *(const float4*)&g_vn[(i0 + r) * C_DIM + cc];
    }
    if (tid >= 16 && tid < 32) misc[tid] = 0.f;   // clear [16..31]
    __syncthreads();
    {   // denominators: sum_j exp(sim[r][j])   (sim in [0,~], offset-0 softmax)
        int r = wrp & 7, half = wrp >> 3;
        float s = 0.f;
        for (int j = half * 1000 + lane * 4; j < half * 1000 + 1000; j += 128) {
            float4 sb = *(const float4*)&simb[r * 2000 + j];
            s += __expf(sb.x) + __expf(sb.y) + __expf(sb.z) + __expf(sb.w);
        }
        s = warpSum(s);
        if (lane == 0) atomicAdd(&misc[16 + r], s);
    }
    __syncthreads();
    if (tid < 8) misc[16 + tid] = 1.0f / misc[16 + tid];
    __syncthreads();
    {   // stream vnt from L2: raw rows, then mask + exp + renorm prep
        int j = tid * 4;
        float tot[ROWS];
        #pragma unroll
        for (int r = 0; r < ROWS; ++r) tot[r] = 0.f;
        if (j < N_TOK) {
            float c[ROWS][4];
            #pragma unroll
            for (int r = 0; r < ROWS; ++r) { c[r][0]=0.f; c[r][1]=0.f; c[r][2]=0.f; c[r][3]=0.f; }
            const float* vt = g_vnt + j;
            float4 kv0 = *(const float4*)&vt[0 * KT_LD];
            float4 kv1 = *(const float4*)&vt[1 * KT_LD];
            float4 kv2 = *(const float4*)&vt[2 * KT_LD];
            float4 kv3 = *(const float4*)&vt[3 * KT_LD];
            for (int ch = 0; ch < 64; ++ch) {
                float4 n0, n1, n2, n3;
                if (ch < 63) {
                    const float* p = vt + (size_t)((ch + 1) * 4) * KT_LD;
                    n0 = *(const float4*)&p[0 * KT_LD];
                    n1 = *(const float4*)&p[1 * KT_LD];
                    n2 = *(const float4*)&p[2 * KT_LD];
                    n3 = *(const float4*)&p[3 * KT_LD];
                }
                #pragma unroll
                for (int r = 0; r < ROWS; ++r) {
                    float4 q = *(const float4*)&scrv[r * 256 + ch * 4];
                    c[r][0] = fmaf(q.x, kv0.x, c[r][0]); c[r][0] = fmaf(q.y, kv1.x, c[r][0]);
                    c[r][0] = fmaf(q.z, kv2.x, c[r][0]); c[r][0] = fmaf(q.w, kv3.x, c[r][0]);
                    c[r][1] = fmaf(q.x, kv0.y, c[r][1]); c[r][1] = fmaf(q.y, kv1.y, c[r][1]);
                    c[r][1] = fmaf(q.z, kv2.y, c[r][1]); c[r][1] = fmaf(q.w, kv3.y, c[r][1]);
                    c[r][2] = fmaf(q.x, kv0.z, c[r][2]); c[r][2] = fmaf(q.y, kv1.z, c[r][2]);
                    c[r][2] = fmaf(q.z, kv2.z, c[r][2]); c[r][2] = fmaf(q.w, kv3.z, c[r][2]);
                    c[r][3] = fmaf(q.x, kv0.w, c[r][3]); c[r][3] = fmaf(q.y, kv1.w, c[r][3]);
                    c[r][3] = fmaf(q.z, kv2.w, c[r][3]); c[r][3] = fmaf(q.w, kv3.w, c[r][3]);
                }
                kv0 = n0; kv1 = n1; kv2 = n2; kv3 = n3;
            }
            #pragma unroll
            for (int r = 0; r < ROWS; ++r) {
                float4 sb = *(const float4*)&simb[r * 2000 + j];
                float inv = misc[16 + r];
                // raw_mean > 0.75  <=>  raw (sum over 8 heads) > 6.0
                float t0 = (c[r][0] > 6.0f) ? __expf(sb.x) * inv : 0.f;
                float t1 = (c[r][1] > 6.0f) ? __expf(sb.y) * inv : 0.f;
                float t2 = (c[r][2] > 6.0f) ? __expf(sb.z) * inv : 0.f;
                float t3 = (c[r][3] > 6.0f) ? __expf(sb.w) * inv : 0.f;
                sb.x = t0; sb.y = t1; sb.z = t2; sb.w = t3;
                *(float4*)&simb[r * 2000 + j] = sb;
                tot[r] += (t0 + t1) + (t2 + t3);
            }
        }
        #pragma unroll
        for (int r = 0; r < ROWS; ++r) {
            float s = warpSum(tot[r]);
            if (lane == 0) atomicAdd(&misc[24 + r], s);
        }
    }
    __syncthreads();
    if (tid < 8) misc[24 + tid] = 1.0f / (misc[24 + tid] + 1e-8f);
    __syncthreads();
    {   // final store
        int r = wrp & 7, half = wrp >> 3;
        float inv = misc[24 + r];
        for (int j = half * 1000 + lane * 4; j < half * 1000 + 1000; j += 128) {
            float4 sb = *(const float4*)&simb[r * 2000 + j];
            sb.x *= inv; sb.y *= inv; sb.z *= inv; sb.w *= inv;
            *(float4*)&out_sim[(size_t)(i0 + r) * 2000 + j] = sb;
        }
    }
}

// ---------------- launch ----------------
extern "C" void kernel_launch(void* const* d_in, const int* in_sizes, int n_in,
                              void* d_out, int out_size) {
    const float* x_cls = (const float*)d_in[0];
    const float* x_reg = (const float*)d_in[1];
    const float* Wc    = (const float*)d_in[2];
    const float* Wr    = (const float*)d_in[3];
    float* out     = (float*)d_out;
    float* out_sim = out + (size_t)N_TOK * 512;

    float *yc, *yr;
    cudaGetSymbolAddress((void**)&yc, g_yc);
    cudaGetSymbolAddress((void**)&yr, g_yr);

    cudaFuncSetAttribute(fused_attn, cudaFuncAttributeMaxDynamicSharedMemorySize,
                         SMEM_FLOATS * 4);

    // 1) QKV projections
    sgemm_nn<<<dim3(12, 32), 256>>>(x_cls, Wc, yc, N_TOK, C3, C_DIM, C_DIM, C3, C3);
    sgemm_nn<<<dim3(12, 32), 256>>>(x_reg, Wr, yr, N_TOK, C3, C_DIM, C_DIM, C3, C3);

    // 2) per-head L2 normalize + transposes (+ x_ori half of out)
    normalize_kernel<<<N_TOK, 256>>>(yc, yr, out);

    // 3) fully fused attention: scores -> softmax -> mask -> sim -> AV -> raw -> sim_round2
    fused_attn<<<NCTA, TPB, SMEM_FLOATS * 4>>>(out, out_sim);
}

// round 12
// speedup vs baseline: 1.9193x; 1.0596x over previous
#include <cuda_runtime.h>
#include <math.h>

#define N_TOK 2000
#define C_DIM 256
#define C3    768
#define H_NUM 8
#define ROWS  8
#define NCTA  250
#define TPB   512
#define KT_LD 2048   // padded j-stride of transposed operands

// ---------------- scratch (static device globals; no allocation) ----------------
static __device__ float g_yc [N_TOK * C3];        // qkv_cls [2000,768]
static __device__ float g_yr [N_TOK * C3];        // qkv_reg
static __device__ float g_qnc[N_TOK * C_DIM];     // normalized q_cls, row-major
static __device__ float g_qnr[N_TOK * C_DIM];
static __device__ float g_vn [N_TOK * C_DIM];     // normalized v_cls, row-major
static __device__ float g_ktc[C_DIM * KT_LD];     // normalized k_cls, TRANSPOSED [chan][j]
static __device__ float g_ktr[C_DIM * KT_LD];     // normalized k_reg, transposed
static __device__ float g_vnt[C_DIM * KT_LD];     // normalized v_cls, transposed

__device__ __forceinline__ float warpSum(float v) {
    #pragma unroll
    for (int o = 16; o; o >>= 1) v += __shfl_xor_sync(0xffffffffu, v, o);
    return v;
}

// ---------------- packed fp32x2 helpers (Blackwell FFMA2, PTX-only) ----------------
__device__ __forceinline__ unsigned long long fma2(unsigned long long a,
                                                   unsigned long long b,
                                                   unsigned long long c) {
    unsigned long long d;
    asm("fma.rn.f32x2 %0, %1, %2, %3;" : "=l"(d) : "l"(a), "l"(b), "l"(c));
    return d;
}
__device__ __forceinline__ unsigned long long pack2(float lo, float hi) {
    unsigned long long d;
    asm("mov.b64 %0, {%1, %2};" : "=l"(d) : "f"(lo), "f"(hi));
    return d;
}
__device__ __forceinline__ float2 unpack2(unsigned long long v) {
    float2 r;
    asm("mov.b64 {%0, %1}, %2;" : "=f"(r.x), "=f"(r.y) : "l"(v));
    return r;
}

// ---------------- GEMM NN:  C[M,N] = A[M,K] * B[K,N] ----------------
__global__ void sgemm_nn(const float* __restrict__ A, const float* __restrict__ B,
                         float* __restrict__ C, int M, int Nn, int K,
                         int lda, int ldb, int ldc) {
    __shared__ float As[64][33];
    __shared__ float Bs[32][65];
    int tid = threadIdx.x;
    int tx = tid & 15, ty = tid >> 4;
    int m0 = blockIdx.y * 64, n0 = blockIdx.x * 64;
    float acc[4][4] = {};
    for (int k0 = 0; k0 < K; k0 += 32) {
        #pragma unroll
        for (int p = 0; p < 8; ++p) {
            int idx = tid + p * 256;
            int r = idx >> 5, k = idx & 31;
            As[r][k] = (m0 + r < M) ? A[(size_t)(m0 + r) * lda + k0 + k] : 0.f;
            int kk = idx >> 6, nn = idx & 63;
            if (kk < 32)
                Bs[kk][nn] = (n0 + nn < Nn) ? B[(size_t)(k0 + kk) * ldb + n0 + nn] : 0.f;
        }
        __syncthreads();
        #pragma unroll
        for (int k = 0; k < 32; ++k) {
            float ra[4], rb[4];
            #pragma unroll
            for (int x = 0; x < 4; ++x) { ra[x] = As[ty * 4 + x][k]; rb[x] = Bs[k][tx * 4 + x]; }
            #pragma unroll
            for (int mi = 0; mi < 4; ++mi)
                #pragma unroll
                for (int ni = 0; ni < 4; ++ni) acc[mi][ni] += ra[mi] * rb[ni];
        }
        __syncthreads();
    }
    #pragma unroll
    for (int mi = 0; mi < 4; ++mi) {
        int gm = m0 + ty * 4 + mi;
        if (gm >= M) continue;
        #pragma unroll
        for (int ni = 0; ni < 4; ++ni) {
            int gn = n0 + tx * 4 + ni;
            if (gn < Nn) C[(size_t)gm * ldc + gn] = acc[mi][ni];
        }
    }
}

// ---------------- per-head L2 normalize + transposes + x_ori ----------------
__device__ __forceinline__ float normed_val(const float* __restrict__ src, int base, int t) {
    float v = src[base + t];
    float ss = warpSum(v * v);          // warp == one 32-dim head segment
    return v / (sqrtf(ss) + 1e-8f);
}
__global__ void normalize_kernel(const float* __restrict__ yc, const float* __restrict__ yr,
                                 float* __restrict__ out) {
    int n = blockIdx.x;
    int t = threadIdx.x;                // 256 threads, 8 warps == 8 heads
    int b = n * C3;
    float qc = normed_val(yc, b + 0,   t);  g_qnc[n * C_DIM + t] = qc;
    float kc = normed_val(yc, b + 256, t);  g_ktc[t * KT_LD + n] = kc;
    float vv = normed_val(yc, b + 512, t);  g_vn[n * C_DIM + t] = vv;
                                            g_vnt[t * KT_LD + n] = vv;
    float qr = normed_val(yr, b + 0,   t);  g_qnr[n * C_DIM + t] = qr;
    float kr = normed_val(yr, b + 256, t);  g_ktr[t * KT_LD + n] = kr;
    out[(size_t)n * 512 + 256 + t] = yc[b + 512 + t];   // x_ori half of x_out
}

// ================= mega-fused attention kernel (f32x2 register-tiled) =================
// smem float layout:
//   [0     .. 16000) expc  (8 rows x 2000)   -> becomes combined masked p in phase B
//   [16000 .. 32000) expr
//   [32000 .. 48000) simb  (8 rows x 2000)
//   [48000 .. 49024) qsd   (phase A: 2 br x 8 rows x 32 ch, DUPLICATED float2)
//   [48000 .. 52096) scrvd (phase C: 8 vn rows x 256 ch, DUPLICATED float2) — overlaps qsd
//   [52096 .. 56192) pav   (AV partials: 16 warps x 8r x 32d)
//   [56192 .. 56224) misc: [0..7] cls inv, [8..15] reg inv, [16..23] s2 inv, [24..31] tot inv
#define SMEM_FLOATS 56224

__global__ __launch_bounds__(TPB, 1) void fused_attn(float* __restrict__ out,
                                                     float* __restrict__ out_sim) {
    extern __shared__ float sm[];
    float* expc = sm;
    float* expr = sm + 16000;
    float* simb = sm + 32000;
    unsigned long long* qsd   = (unsigned long long*)(sm + 48000);
    unsigned long long* scrvd = (unsigned long long*)(sm + 48000);
    float* pav  = sm + 52096;
    float* misc = sm + 56192;

    const int tid  = threadIdx.x;
    const int lane = tid & 31;
    const int wrp  = tid >> 5;
    const int i0   = blockIdx.x * ROWS;

    // phase A map: branch x 256 j-threads (4 j each, 2 passes)
    const int bA = tid >> 8;            // 0=cls, 1=reg (warp-uniform)
    const int jt = tid & 255;
    const float* ktA = bA ? g_ktr : g_ktc;
    float* ebA = bA ? expr : expc;
    const int boff = bA * 256;

    // zero sim accumulator
    for (int k = tid; k < ROWS * N_TOK; k += TPB) simb[k] = 0.f;

    for (int h = 0; h < H_NUM; ++h) {
        // ======== phase A: scores -> exp -> row sums (k streamed from L2, FFMA2) ========
        if (tid < 16) misc[tid] = 0.f;
        {   // load q tiles duplicated: 512 entries = 2 branches x 8 rows x 32 ch
            int b2 = tid >> 8, r = (tid >> 5) & 7, kk = tid & 31;
            const float* qsrc = b2 ? g_qnr : g_qnc;
            float q = qsrc[(i0 + r) * C_DIM + h * 32 + kk];
            qsd[tid] = pack2(q, q);
        }
        __syncthreads();

        float psum[ROWS];
        #pragma unroll
        for (int r = 0; r < ROWS; ++r) psum[r] = 0.f;

        #pragma unroll
        for (int pass = 0; pass < 2; ++pass) {
            int j = pass * 1024 + jt * 4;
            if (j < N_TOK) {
                unsigned long long c2[ROWS][2];
                #pragma unroll
                for (int r = 0; r < ROWS; ++r) { c2[r][0] = 0ULL; c2[r][1] = 0ULL; }
                const float* ktb = ktA + (size_t)(h * 32) * KT_LD + j;
                for (int cg = 0; cg < 8; ++cg) {
                    ulonglong2 kv[4];
                    #pragma unroll
                    for (int u = 0; u < 4; ++u)
                        kv[u] = *(const ulonglong2*)&ktb[(size_t)(cg * 4 + u) * KT_LD];
                    #pragma unroll
                    for (int u = 0; u < 4; ++u) {
                        #pragma unroll
                        for (int r = 0; r < ROWS; ++r) {
                            unsigned long long qd = qsd[boff + r * 32 + cg * 4 + u];
                            c2[r][0] = fma2(qd, kv[u].x, c2[r][0]);
                            c2[r][1] = fma2(qd, kv[u].y, c2[r][1]);
                        }
                    }
                }
                #pragma unroll
                for (int r = 0; r < ROWS; ++r) {
                    float2 lo = unpack2(c2[r][0]);
                    float2 hi = unpack2(c2[r][1]);
                    float4 e;
                    e.x = __expf(fmaf(lo.x, 25.f, -25.f));
                    e.y = __expf(fmaf(lo.y, 25.f, -25.f));
                    e.z = __expf(fmaf(hi.x, 25.f, -25.f));
                    e.w = __expf(fmaf(hi.y, 25.f, -25.f));
                    *(float4*)&ebA[r * 2000 + j] = e;
                    psum[r] += (e.x + e.y) + (e.z + e.w);
                }
            }
        }
        #pragma unroll
        for (int r = 0; r < ROWS; ++r) {
            float s = warpSum(psum[r]);
            if (lane == 0) atomicAdd(&misc[bA * 8 + r], s);
        }
        __syncthreads();
        if (tid < 16) misc[tid] = 1.0f / misc[tid];
        __syncthreads();

        // ======== phase B1: combine + mask (p overwrites expc) + sim accumulate ========
        for (int idx = tid; idx < 4000; idx += TPB) {   // 4000 float4 groups
            int r = idx / 500;
            int j = (idx - r * 500) * 4;
            float4 ec = *(const float4*)&expc[r * 2000 + j];
            float4 er = *(const float4*)&expr[r * 2000 + j];
            float ic = misc[r], ir = misc[8 + r];
            float4 p;
            p.x = 0.5f * fmaf(ec.x, ic, er.x * ir);
            p.y = 0.5f * fmaf(ec.y, ic, er.y * ir);
            p.z = 0.5f * fmaf(ec.z, ic, er.z * ir);
            p.w = 0.5f * fmaf(ec.w, ic, er.w * ir);
            int i = i0 + r, bs = (i / 10) * 10;
            if (!((j + 0 == i) || (j + 0 < bs) || (j + 0 >= bs + 9))) p.x = 0.f;
            if (!((j + 1 == i) || (j + 1 < bs) || (j + 1 >= bs + 9))) p.y = 0.f;
            if (!((j + 2 == i) || (j + 2 < bs) || (j + 2 >= bs + 9))) p.z = 0.f;
            if (!((j + 3 == i) || (j + 3 < bs) || (j + 3 >= bs + 9))) p.w = 0.f;
            float4 sb = *(const float4*)&simb[r * 2000 + j];
            sb.x += p.x; sb.y += p.y; sb.z += p.z; sb.w += p.w;
            *(float4*)&simb[r * 2000 + j] = sb;
            *(float4*)&expc[r * 2000 + j] = p;
        }
        __syncthreads();

        // ======== phase B2: AV (x = p @ v), 16 warps x 128-j slices, FFMA2 ========
        {
            int jbase = wrp * 128;
            int cnt = N_TOK - jbase; if (cnt > 128) cnt = 128;
            unsigned long long acc2[ROWS];
            #pragma unroll
            for (int r = 0; r < ROWS; ++r) acc2[r] = 0ULL;
            const float* vp = g_yc + 512 + h * 32 + lane;
            for (int jj = 0; jj < cnt; jj += 4) {
                int j = jbase + jj;
                float v0 = vp[(size_t)(j + 0) * C3];
                float v1 = vp[(size_t)(j + 1) * C3];
                float v2 = vp[(size_t)(j + 2) * C3];
                float v3 = vp[(size_t)(j + 3) * C3];
                unsigned long long vA = pack2(v0, v1);
                unsigned long long vB = pack2(v2, v3);
                #pragma unroll
                for (int r = 0; r < ROWS; ++r) {
                    ulonglong2 p2 = *(const ulonglong2*)&expc[r * 2000 + j];  // broadcast
                    acc2[r] = fma2(p2.x, vA, acc2[r]);
                    acc2[r] = fma2(p2.y, vB, acc2[r]);
                }
            }
            #pragma unroll
            for (int r = 0; r < ROWS; ++r) {
                float2 t = unpack2(acc2[r]);
                pav[wrp * 256 + r * 32 + lane] = t.x + t.y;
            }
        }
        __syncthreads();
        if (tid < 256) {
            int r = tid >> 5, d = tid & 31;
            float s = 0.f;
            #pragma unroll
            for (int w2 = 0; w2 < 16; ++w2) s += pav[w2 * 256 + tid];
            out[(size_t)(i0 + r) * 512 + h * 32 + d] = s;
        }
        __syncthreads();
    }

    // ======== phase C: raw = vn.vn^T mask + sim_round2 (FFMA2) ========
    {   // vn rows of this block -> scrvd duplicated (8 x 256 float2)
        int r = tid >> 6, cc = (tid & 63) * 4;
        float4 v = *(const float4*)&g_vn[(i0 + r) * C_DIM + cc];
        scrvd[r * 256 + cc + 0] = pack2(v.x, v.x);
        scrvd[r * 256 + cc + 1] = pack2(v.y, v.y);
        scrvd[r * 256 + cc + 2] = pack2(v.z, v.z);
        scrvd[r * 256 + cc + 3] = pack2(v.w, v.w);
    }
    if (tid >= 16 && tid < 32) misc[tid] = 0.f;   // clear [16..31]
    __syncthreads();
    {   // denominators: sum_j exp(sim[r][j])
        int r = wrp & 7, half = wrp >> 3;
        float s = 0.f;
        for (int j = half * 1000 + lane * 4; j < half * 1000 + 1000; j += 128) {
            float4 sb = *(const float4*)&simb[r * 2000 + j];
            s += __expf(sb.x) + __expf(sb.y) + __expf(sb.z) + __expf(sb.w);
        }
        s = warpSum(s);
        if (lane == 0) atomicAdd(&misc[16 + r], s);
    }
    __syncthreads();
    if (tid < 8) misc[16 + tid] = 1.0f / misc[16 + tid];
    __syncthreads();
    {   // stream vnt from L2: raw rows, then mask + exp + renorm prep
        int j = tid * 4;
        float tot[ROWS];
        #pragma unroll
        for (int r = 0; r < ROWS; ++r) tot[r] = 0.f;
        if (j < N_TOK) {
            unsigned long long c2[ROWS][2];
            #pragma unroll
            for (int r = 0; r < ROWS; ++r) { c2[r][0] = 0ULL; c2[r][1] = 0ULL; }
            const float* vt = g_vnt + j;
            for (int cg = 0; cg < 64; ++cg) {
                ulonglong2 kv[4];
                #pragma unroll
                for (int u = 0; u < 4; ++u)
                    kv[u] = *(const ulonglong2*)&vt[(size_t)(cg * 4 + u) * KT_LD];
                #pragma unroll
                for (int u = 0; u < 4; ++u) {
                    #pragma unroll
                    for (int r = 0; r < ROWS; ++r) {
                        unsigned long long qd = scrvd[r * 256 + cg * 4 + u];
                        c2[r][0] = fma2(qd, kv[u].x, c2[r][0]);
                        c2[r][1] = fma2(qd, kv[u].y, c2[r][1]);
                    }
                }
            }
            #pragma unroll
            for (int r = 0; r < ROWS; ++r) {
                float2 lo = unpack2(c2[r][0]);
                float2 hi = unpack2(c2[r][1]);
                float4 sb = *(const float4*)&simb[r * 2000 + j];
                float inv = misc[16 + r];
                // raw_mean > 0.75  <=>  raw (sum over 8 heads) > 6.0
                float t0 = (lo.x > 6.0f) ? __expf(sb.x) * inv : 0.f;
                float t1 = (lo.y > 6.0f) ? __expf(sb.y) * inv : 0.f;
                float t2 = (hi.x > 6.0f) ? __expf(sb.z) * inv : 0.f;
                float t3 = (hi.y > 6.0f) ? __expf(sb.w) * inv : 0.f;
                sb.x = t0; sb.y = t1; sb.z = t2; sb.w = t3;
                *(float4*)&simb[r * 2000 + j] = sb;
                tot[r] += (t0 + t1) + (t2 + t3);
            }
        }
        #pragma unroll
        for (int r = 0; r < ROWS; ++r) {
            float s = warpSum(tot[r]);
            if (lane == 0) atomicAdd(&misc[24 + r], s);
        }
    }
    __syncthreads();
    if (tid < 8) misc[24 + tid] = 1.0f / (misc[24 + tid] + 1e-8f);
    __syncthreads();
    {   // final store
        int r = wrp & 7, half = wrp >> 3;
        float inv = misc[24 + r];
        for (int j = half * 1000 + lane * 4; j < half * 1000 + 1000; j += 128) {
            float4 sb = *(const float4*)&simb[r * 2000 + j];
            sb.x *= inv; sb.y *= inv; sb.z *= inv; sb.w *= inv;
            *(float4*)&out_sim[(size_t)(i0 + r) * 2000 + j] = sb;
        }
    }
}

// ---------------- launch ----------------
extern "C" void kernel_launch(void* const* d_in, const int* in_sizes, int n_in,
                              void* d_out, int out_size) {
    const float* x_cls = (const float*)d_in[0];
    const float* x_reg = (const float*)d_in[1];
    const float* Wc    = (const float*)d_in[2];
    const float* Wr    = (const float*)d_in[3];
    float* out     = (float*)d_out;
    float* out_sim = out + (size_t)N_TOK * 512;

    float *yc, *yr;
    cudaGetSymbolAddress((void**)&yc, g_yc);
    cudaGetSymbolAddress((void**)&yr, g_yr);

    cudaFuncSetAttribute(fused_attn, cudaFuncAttributeMaxDynamicSharedMemorySize,
                         SMEM_FLOATS * 4);

    // 1) QKV projections
    sgemm_nn<<<dim3(12, 32), 256>>>(x_cls, Wc, yc, N_TOK, C3, C_DIM, C_DIM, C3, C3);
    sgemm_nn<<<dim3(12, 32), 256>>>(x_reg, Wr, yr, N_TOK, C3, C_DIM, C_DIM, C3, C3);

    // 2) per-head L2 normalize + transposes (+ x_ori half of out)
    normalize_kernel<<<N_TOK, 256>>>(yc, yr, out);

    // 3) fully fused attention: scores -> softmax -> mask -> sim -> AV -> raw -> sim_round2
    fused_attn<<<NCTA, TPB, SMEM_FLOATS * 4>>>(out, out_sim);
}